// round 9
// baseline (speedup 1.0000x reference)
#include <cuda_runtime.h>
#include <cuda_fp16.h>
#include <math.h>
#include <cstdint>

#define BATCH 4
#define SEQ   2048
#define DM    1024
#define NH    64

// ---------------- scratch (no cudaMalloc allowed) ----------------
__device__ __half g_q[BATCH * SEQ * NH];    // fp16, pre-scaled by 0.125
__device__ __half g_k[BATCH * SEQ * NH];    // fp16
__device__ __half g_v[BATCH * SEQ * NH];    // fp16 row-major [s][h]
__device__ __half g_vt[BATCH * NH * SEQ];   // fp16 transposed [h][s]
__device__ __half g_wt[192 * DM];           // W^T (q|k|v rows), fp16

// mma.sync m16n8k16 fp16 (sm_80+ PTX; tensor pipe)
__device__ __forceinline__ void mma_f16(float d[4], const uint32_t a[4],
                                        uint32_t b0, uint32_t b1) {
    asm volatile(
        "mma.sync.aligned.m16n8k16.row.col.f32.f16.f16.f32 "
        "{%0,%1,%2,%3}, {%4,%5,%6,%7}, {%8,%9}, {%0,%1,%2,%3};\n"
        : "+f"(d[0]), "+f"(d[1]), "+f"(d[2]), "+f"(d[3])
        : "r"(a[0]), "r"(a[1]), "r"(a[2]), "r"(a[3]), "r"(b0), "r"(b1));
}

__device__ __forceinline__ uint2 c4h(float4 v) {
    __half2 a = __floats2half2_rn(v.x, v.y);
    __half2 b = __floats2half2_rn(v.z, v.w);
    uint2 r;
    r.x = *(uint32_t*)&a;
    r.y = *(uint32_t*)&b;
    return r;
}

// =================================================================
// Kernel 0: transpose W (q|k|v) -> g_wt[192][1024] fp16.
// =================================================================
__global__ __launch_bounds__(256) void wt_kernel(
    const float* __restrict__ Wq,
    const float* __restrict__ Wk,
    const float* __restrict__ Wv)
{
    __shared__ float t[64][65];
    const int tid = threadIdx.x;
    const int k0  = blockIdx.x * 64;
    const int y   = blockIdx.y;
    const float* W = (y == 0) ? Wq : (y == 1) ? Wk : Wv;

    #pragma unroll
    for (int i = 0; i < 16; i++) {
        const int idx = tid + i * 256;
        const int kk = idx >> 6, nn = idx & 63;
        t[kk][nn] = W[(k0 + kk) * NH + nn];
    }
    __syncthreads();
    #pragma unroll
    for (int i = 0; i < 16; i++) {
        const int idx = tid + i * 256;
        const int nn = idx >> 6, kk = idx & 63;
        g_wt[(y * 64 + nn) * DM + k0 + kk] = __float2half(t[kk][nn]);
    }
}

// =================================================================
// Kernel 1: QKV projection, fp16 m16n8k16.
// Block: M=64 x N=192, 8 warps (2x4), warp tile 32x48.
// K=1024 in 32-chunks; double-buffered fp16 smem, 1 barrier/chunk,
// 2-deep global prefetch. Outputs fp16 (q pre-scaled by 0.125).
// =================================================================
#define QST 40   // smem row stride in halfs (bank-verified)

__global__ __launch_bounds__(256) void qkv_mma_kernel(
    const float* __restrict__ x,
    const float* __restrict__ bq,
    const float* __restrict__ bk,
    const float* __restrict__ bv)
{
    __shared__ __half As[2][64][QST];
    __shared__ __half Bs[2][192][QST];
    __shared__ float bias_sm[192];

    const int tid  = threadIdx.x;
    const int wid  = tid >> 5;
    const int lane = tid & 31;
    const int m0   = blockIdx.x * 64;
    const int wm   = wid >> 2;
    const int wn   = wid & 3;
    const int gid  = lane >> 2;
    const int tig  = lane & 3;

    if (tid < 64)        bias_sm[tid] = bq[tid];
    else if (tid < 128)  bias_sm[tid] = bk[tid - 64];
    else if (tid < 192)  bias_sm[tid] = bv[tid - 128];

    float d[2][6][4];
    #pragma unroll
    for (int i = 0; i < 2; i++)
        #pragma unroll
        for (int j = 0; j < 6; j++)
            #pragma unroll
            for (int c = 0; c < 4; c++) d[i][j][c] = 0.f;

    // x load: idx=tid+256i (i<2): row=idx>>3, seg=idx&7 (4 f32 each)
    // W load: idx=tid+256i (i<3): row=idx>>2, seg=idx&3 (8 halfs each)
    float4 rx[2][2];
    uint4  rw[2][3];

    auto ldg_chunk = [&](int c, int slot) {
        const int kc = c * 32;
        #pragma unroll
        for (int i = 0; i < 2; i++) {
            const int idx = tid + 256 * i;
            rx[slot][i] = *(const float4*)&x[(size_t)(m0 + (idx >> 3)) * DM + kc + (idx & 7) * 4];
        }
        #pragma unroll
        for (int i = 0; i < 3; i++) {
            const int idx = tid + 256 * i;
            rw[slot][i] = *(const uint4*)&g_wt[(size_t)(idx >> 2) * DM + kc + (idx & 3) * 8];
        }
    };
    auto commit_chunk = [&](int slot, int buf) {
        #pragma unroll
        for (int i = 0; i < 2; i++) {
            const int idx = tid + 256 * i;
            *(uint2*)&As[buf][idx >> 3][(idx & 7) * 4] = c4h(rx[slot][i]);
        }
        #pragma unroll
        for (int i = 0; i < 3; i++) {
            const int idx = tid + 256 * i;
            *(uint4*)&Bs[buf][idx >> 2][(idx & 3) * 8] = rw[slot][i];
        }
    };

    const int NC = DM / 32;  // 32 chunks
    ldg_chunk(0, 0);
    ldg_chunk(1, 1);
    commit_chunk(0, 0);
    ldg_chunk(2, 0);
    __syncthreads();

    for (int it = 0; it < NC; it++) {
        const int buf = it & 1;
        #pragma unroll
        for (int ks = 0; ks < 2; ks++) {
            const int k0 = ks * 16;
            uint32_t a[2][4];
            #pragma unroll
            for (int mt = 0; mt < 2; mt++) {
                const int r = wm * 32 + mt * 16 + gid;
                a[mt][0] = *(const uint32_t*)&As[buf][r][k0 + 2 * tig];
                a[mt][1] = *(const uint32_t*)&As[buf][r + 8][k0 + 2 * tig];
                a[mt][2] = *(const uint32_t*)&As[buf][r][k0 + 2 * tig + 8];
                a[mt][3] = *(const uint32_t*)&As[buf][r + 8][k0 + 2 * tig + 8];
            }
            #pragma unroll
            for (int nt = 0; nt < 6; nt++) {
                const int n = wn * 48 + nt * 8 + gid;
                const uint32_t b0 = *(const uint32_t*)&Bs[buf][n][k0 + 2 * tig];
                const uint32_t b1 = *(const uint32_t*)&Bs[buf][n][k0 + 2 * tig + 8];
                mma_f16(d[0][nt], a[0], b0, b1);
                mma_f16(d[1][nt], a[1], b0, b1);
            }
        }
        if (it + 1 < NC) commit_chunk((it + 1) & 1, (it + 1) & 1);
        if (it + 3 < NC) ldg_chunk(it + 3, (it + 1) & 1);
        __syncthreads();
    }

    // epilogue: bias + (scale q) + fp16 store
    #pragma unroll
    for (int mt = 0; mt < 2; mt++) {
        const int row = m0 + wm * 32 + mt * 16 + gid;
        #pragma unroll
        for (int nt = 0; nt < 6; nt++) {
            const int col0 = wn * 48 + nt * 8;
            __half* dst = (col0 < 64) ? g_q : (col0 < 128) ? g_k : g_v;
            const float scale = (col0 < 64) ? 0.125f : 1.0f;
            const int h0 = (col0 & 63) + 2 * tig;
            const float b0 = bias_sm[col0 + 2 * tig];
            const float b1 = bias_sm[col0 + 2 * tig + 1];
            __half2 w0 = __floats2half2_rn((d[mt][nt][0] + b0) * scale,
                                           (d[mt][nt][1] + b1) * scale);
            __half2 w1 = __floats2half2_rn((d[mt][nt][2] + b0) * scale,
                                           (d[mt][nt][3] + b1) * scale);
            *(uint32_t*)&dst[(size_t)row * NH + h0]       = *(uint32_t*)&w0;
            *(uint32_t*)&dst[(size_t)(row + 8) * NH + h0] = *(uint32_t*)&w1;
        }
    }
}

// =================================================================
// Kernel 1b: transpose V -> g_vt [b][h][s] fp16.
// =================================================================
__global__ __launch_bounds__(256) void vt_kernel()
{
    __shared__ __half t[64][72];
    const int tid = threadIdx.x;
    const int s0  = blockIdx.x * 64;
    const int b   = blockIdx.y;
    const __half* src = g_v + (size_t)b * SEQ * NH;
    __half* dst = g_vt + (size_t)b * NH * SEQ;

    #pragma unroll
    for (int i = 0; i < 2; i++) {
        const int idx = tid + 256 * i;
        const int row = idx >> 3, seg = (idx & 7) * 8;
        *(uint4*)&t[row][seg] = *(const uint4*)&src[(size_t)(s0 + row) * NH + seg];
    }
    __syncthreads();
    #pragma unroll
    for (int i = 0; i < 2; i++) {
        const int idx = tid + 256 * i;
        const int h = idx >> 3, seg = (idx & 7) * 8;
        uint32_t w[4];
        #pragma unroll
        for (int j = 0; j < 4; j++) {
            __half2 hh = __halves2half2(t[seg + 2 * j][h], t[seg + 2 * j + 1][h]);
            w[j] = *(uint32_t*)&hh;
        }
        uint4 o = make_uint4(w[0], w[1], w[2], w[3]);
        *(uint4*)&dst[(size_t)h * SEQ + s0 + seg] = o;
    }
}

// =================================================================
// Kernel 2: causal flash attention, fp16 m16n8k16.
// 64-thread blocks (2 warps), BQ=32, BK=64, warp tile m16 x n64.
// Warp-local softmax (quad shuffles, stats in regs), P in registers
// (S-output frag == PV A-frag), 1 barrier/tile, 256 blocks
// (heavy qtiles first) -> multiple blocks/SM hide softmax phases.
// =================================================================
#define AST 72   // kv/q smem row stride in halfs (bank-verified)

__global__ __launch_bounds__(64) void attn_kernel(float* __restrict__ out)
{
    __shared__ __half ks[2][64][AST];
    __shared__ __half vs[2][64][AST];

    const int tid = threadIdx.x;
    const int qt  = 63 - blockIdx.x;      // heavy blocks first
    const int b   = blockIdx.y;
    const int q0  = qt * 32;
    const int nk  = (qt >> 1) + 1;

    const __half* Q  = g_q  + (size_t)b * SEQ * NH;
    const __half* K  = g_k  + (size_t)b * SEQ * NH;
    const __half* VT = g_vt + (size_t)b * NH * SEQ;

    const int wid  = tid >> 5;
    const int lane = tid & 31;
    const int gid  = lane >> 2;
    const int tig  = lane & 3;
    const int r0   = wid * 16 + gid;
    const int r1   = r0 + 8;

    // Q A-fragments straight from global (once per block)
    uint32_t qa[4][4];
    #pragma unroll
    for (int kc = 0; kc < 4; kc++) {
        const __half* p0 = &Q[(size_t)(q0 + r0) * NH + kc * 16 + 2 * tig];
        const __half* p1 = &Q[(size_t)(q0 + r1) * NH + kc * 16 + 2 * tig];
        qa[kc][0] = *(const uint32_t*)p0;
        qa[kc][1] = *(const uint32_t*)p1;
        qa[kc][2] = *(const uint32_t*)(p0 + 8);
        qa[kc][3] = *(const uint32_t*)(p1 + 8);
    }

    // copy tile 0 (K row-major, V^T h-major)
    #pragma unroll
    for (int i = 0; i < 8; i++) {
        const int idx = tid + 64 * i;
        const int row = idx >> 3, seg = (idx & 7) * 8;
        *(uint4*)&ks[0][row][seg] = *(const uint4*)&K[(size_t)row * NH + seg];
        *(uint4*)&vs[0][row][seg] = *(const uint4*)&VT[(size_t)row * SEQ + seg];
    }
    __syncthreads();

    float m0 = -1e30f, m1 = -1e30f, l0 = 0.f, l1 = 0.f;
    float d_o[8][4];
    #pragma unroll
    for (int nt = 0; nt < 8; nt++)
        #pragma unroll
        for (int c = 0; c < 4; c++) d_o[nt][c] = 0.f;

    for (int t = 0; t < nk; t++) {
        // copy tile t+1 into the other buffer (covered by this tile's compute)
        if (t + 1 < nk) {
            const int kb = (t + 1) * 64;
            const int bn = (t + 1) & 1;
            #pragma unroll
            for (int i = 0; i < 8; i++) {
                const int idx = tid + 64 * i;
                const int row = idx >> 3, seg = (idx & 7) * 8;
                *(uint4*)&ks[bn][row][seg] =
                    *(const uint4*)&K[(size_t)(kb + row) * NH + seg];
                *(uint4*)&vs[bn][row][seg] =
                    *(const uint4*)&VT[(size_t)row * SEQ + kb + seg];
            }
        }

        // ---- S = Q K^T ----
        float sd[8][4];
        #pragma unroll
        for (int nt = 0; nt < 8; nt++)
            #pragma unroll
            for (int c = 0; c < 4; c++) sd[nt][c] = 0.f;

        {
            const __half (*kt)[AST] = ks[t & 1];
            #pragma unroll
            for (int kc = 0; kc < 4; kc++) {
                #pragma unroll
                for (int nt = 0; nt < 8; nt++) {
                    const __half* kp = &kt[8 * nt + gid][kc * 16 + 2 * tig];
                    mma_f16(sd[nt], qa[kc],
                            *(const uint32_t*)kp, *(const uint32_t*)(kp + 8));
                }
            }
        }

        // ---- causal mask (diagonal tile only) ----
        if (t == nk - 1) {
            #pragma unroll
            for (int nt = 0; nt < 8; nt++) {
                const int kg = t * 64 + 8 * nt + 2 * tig;
                if (kg     > q0 + r0) sd[nt][0] = -1e30f;
                if (kg + 1 > q0 + r0) sd[nt][1] = -1e30f;
                if (kg     > q0 + r1) sd[nt][2] = -1e30f;
                if (kg + 1 > q0 + r1) sd[nt][3] = -1e30f;
            }
        }

        // ---- warp-local online softmax ----
        float t0 = -1e30f, t1 = -1e30f;
        #pragma unroll
        for (int nt = 0; nt < 8; nt++) {
            t0 = fmaxf(t0, fmaxf(sd[nt][0], sd[nt][1]));
            t1 = fmaxf(t1, fmaxf(sd[nt][2], sd[nt][3]));
        }
        t0 = fmaxf(t0, __shfl_xor_sync(0xffffffffu, t0, 1));
        t0 = fmaxf(t0, __shfl_xor_sync(0xffffffffu, t0, 2));
        t1 = fmaxf(t1, __shfl_xor_sync(0xffffffffu, t1, 1));
        t1 = fmaxf(t1, __shfl_xor_sync(0xffffffffu, t1, 2));
        const float mn0 = fmaxf(m0, t0);
        const float mn1 = fmaxf(m1, t1);
        const float f0 = __expf(m0 - mn0);
        const float f1 = __expf(m1 - mn1);
        m0 = mn0; m1 = mn1;
        #pragma unroll
        for (int nt = 0; nt < 8; nt++) {
            d_o[nt][0] *= f0; d_o[nt][1] *= f0;
            d_o[nt][2] *= f1; d_o[nt][3] *= f1;
        }

        uint32_t pa[4][4];
        float s0 = 0.f, s1 = 0.f;
        #pragma unroll
        for (int nt = 0; nt < 8; nt++) {
            __half2 h0 = __floats2half2_rn(__expf(sd[nt][0] - mn0),
                                           __expf(sd[nt][1] - mn0));
            __half2 h1 = __floats2half2_rn(__expf(sd[nt][2] - mn1),
                                           __expf(sd[nt][3] - mn1));
            float2 g0 = __half22float2(h0);
            float2 g1 = __half22float2(h1);
            s0 += g0.x + g0.y;
            s1 += g1.x + g1.y;
            const int kc = nt >> 1;
            if ((nt & 1) == 0) {
                pa[kc][0] = *(uint32_t*)&h0;
                pa[kc][1] = *(uint32_t*)&h1;
            } else {
                pa[kc][2] = *(uint32_t*)&h0;
                pa[kc][3] = *(uint32_t*)&h1;
            }
        }
        s0 += __shfl_xor_sync(0xffffffffu, s0, 1);
        s0 += __shfl_xor_sync(0xffffffffu, s0, 2);
        s1 += __shfl_xor_sync(0xffffffffu, s1, 1);
        s1 += __shfl_xor_sync(0xffffffffu, s1, 2);
        l0 = l0 * f0 + s0;
        l1 = l1 * f1 + s1;

        // ---- O += P V ----
        {
            const __half (*vt)[AST] = vs[t & 1];
            #pragma unroll
            for (int kc = 0; kc < 4; kc++) {
                #pragma unroll
                for (int nt = 0; nt < 8; nt++) {
                    const __half* vp = &vt[8 * nt + gid][kc * 16 + 2 * tig];
                    mma_f16(d_o[nt], pa[kc],
                            *(const uint32_t*)vp, *(const uint32_t*)(vp + 8));
                }
            }
        }
        __syncthreads();
    }

    // ---- normalize + writeout ----
    const float il0 = 1.f / l0;
    const float il1 = 1.f / l1;
    #pragma unroll
    for (int nt = 0; nt < 8; nt++) {
        const int cc = 8 * nt + 2 * tig;
        *(float2*)&out[(size_t)(b * SEQ + q0 + r0) * NH + cc] =
            make_float2(d_o[nt][0] * il0, d_o[nt][1] * il0);
        *(float2*)&out[(size_t)(b * SEQ + q0 + r1) * NH + cc] =
            make_float2(d_o[nt][2] * il1, d_o[nt][3] * il1);
    }
}

// =================================================================
// launch
// =================================================================
extern "C" void kernel_launch(void* const* d_in, const int* in_sizes, int n_in,
                              void* d_out, int out_size)
{
    (void)in_sizes; (void)n_in; (void)out_size;
    const float* x  = (const float*)d_in[0];
    const float* Wq = (const float*)d_in[1];
    const float* bq = (const float*)d_in[2];
    const float* Wk = (const float*)d_in[3];
    const float* bk = (const float*)d_in[4];
    const float* Wv = (const float*)d_in[5];
    const float* bv = (const float*)d_in[6];
    float* out = (float*)d_out;

    wt_kernel<<<dim3(16, 3), 256>>>(Wq, Wk, Wv);
    qkv_mma_kernel<<<(BATCH * SEQ) / 64, 256>>>(x, bq, bk, bv);
    vt_kernel<<<dim3(SEQ / 64, BATCH), 256>>>();
    attn_kernel<<<dim3(64, BATCH), 64>>>(out);
}

// round 10
// speedup vs baseline: 1.1864x; 1.1864x over previous
#include <cuda_runtime.h>
#include <cuda_fp16.h>
#include <math.h>
#include <cstdint>

#define BATCH 4
#define SEQ   2048
#define DM    1024
#define NH    64
#define NSP   4      // key splits per q-tile

// ---------------- scratch (no cudaMalloc allowed) ----------------
__device__ __half g_q[BATCH * SEQ * NH];    // fp16, pre-scaled by 0.125
__device__ __half g_k[BATCH * SEQ * NH];    // fp16
__device__ __half g_v[BATCH * SEQ * NH];    // fp16 row-major [s][h]
__device__ __half g_vt[BATCH * NH * SEQ];   // fp16 transposed [h][s]
__device__ __half g_wt[192 * DM];           // W^T (q|k|v rows), fp16
__device__ float  g_po[BATCH * NSP * SEQ * NH];  // partial O (unnormalized)
__device__ float  g_pm[BATCH * NSP * SEQ];       // partial row max
__device__ float  g_pl[BATCH * NSP * SEQ];       // partial row sum

// mma.sync m16n8k16 fp16 (sm_80+ PTX; tensor pipe)
__device__ __forceinline__ void mma_f16(float d[4], const uint32_t a[4],
                                        uint32_t b0, uint32_t b1) {
    asm volatile(
        "mma.sync.aligned.m16n8k16.row.col.f32.f16.f16.f32 "
        "{%0,%1,%2,%3}, {%4,%5,%6,%7}, {%8,%9}, {%0,%1,%2,%3};\n"
        : "+f"(d[0]), "+f"(d[1]), "+f"(d[2]), "+f"(d[3])
        : "r"(a[0]), "r"(a[1]), "r"(a[2]), "r"(a[3]), "r"(b0), "r"(b1));
}

__device__ __forceinline__ uint2 c4h(float4 v) {
    __half2 a = __floats2half2_rn(v.x, v.y);
    __half2 b = __floats2half2_rn(v.z, v.w);
    uint2 r;
    r.x = *(uint32_t*)&a;
    r.y = *(uint32_t*)&b;
    return r;
}

// =================================================================
// Kernel 0: transpose W (q|k|v) -> g_wt[192][1024] fp16.
// =================================================================
__global__ __launch_bounds__(256) void wt_kernel(
    const float* __restrict__ Wq,
    const float* __restrict__ Wk,
    const float* __restrict__ Wv)
{
    __shared__ float t[64][65];
    const int tid = threadIdx.x;
    const int k0  = blockIdx.x * 64;
    const int y   = blockIdx.y;
    const float* W = (y == 0) ? Wq : (y == 1) ? Wk : Wv;

    #pragma unroll
    for (int i = 0; i < 16; i++) {
        const int idx = tid + i * 256;
        const int kk = idx >> 6, nn = idx & 63;
        t[kk][nn] = W[(k0 + kk) * NH + nn];
    }
    __syncthreads();
    #pragma unroll
    for (int i = 0; i < 16; i++) {
        const int idx = tid + i * 256;
        const int nn = idx >> 6, kk = idx & 63;
        g_wt[(y * 64 + nn) * DM + k0 + kk] = __float2half(t[kk][nn]);
    }
}

// =================================================================
// Kernel 1: QKV projection, fp16 m16n8k16 (unchanged from R9).
// =================================================================
#define QST 40

__global__ __launch_bounds__(256) void qkv_mma_kernel(
    const float* __restrict__ x,
    const float* __restrict__ bq,
    const float* __restrict__ bk,
    const float* __restrict__ bv)
{
    __shared__ __half As[2][64][QST];
    __shared__ __half Bs[2][192][QST];
    __shared__ float bias_sm[192];

    const int tid  = threadIdx.x;
    const int wid  = tid >> 5;
    const int lane = tid & 31;
    const int m0   = blockIdx.x * 64;
    const int wm   = wid >> 2;
    const int wn   = wid & 3;
    const int gid  = lane >> 2;
    const int tig  = lane & 3;

    if (tid < 64)        bias_sm[tid] = bq[tid];
    else if (tid < 128)  bias_sm[tid] = bk[tid - 64];
    else if (tid < 192)  bias_sm[tid] = bv[tid - 128];

    float d[2][6][4];
    #pragma unroll
    for (int i = 0; i < 2; i++)
        #pragma unroll
        for (int j = 0; j < 6; j++)
            #pragma unroll
            for (int c = 0; c < 4; c++) d[i][j][c] = 0.f;

    float4 rx[2][2];
    uint4  rw[2][3];

    auto ldg_chunk = [&](int c, int slot) {
        const int kc = c * 32;
        #pragma unroll
        for (int i = 0; i < 2; i++) {
            const int idx = tid + 256 * i;
            rx[slot][i] = *(const float4*)&x[(size_t)(m0 + (idx >> 3)) * DM + kc + (idx & 7) * 4];
        }
        #pragma unroll
        for (int i = 0; i < 3; i++) {
            const int idx = tid + 256 * i;
            rw[slot][i] = *(const uint4*)&g_wt[(size_t)(idx >> 2) * DM + kc + (idx & 3) * 8];
        }
    };
    auto commit_chunk = [&](int slot, int buf) {
        #pragma unroll
        for (int i = 0; i < 2; i++) {
            const int idx = tid + 256 * i;
            *(uint2*)&As[buf][idx >> 3][(idx & 7) * 4] = c4h(rx[slot][i]);
        }
        #pragma unroll
        for (int i = 0; i < 3; i++) {
            const int idx = tid + 256 * i;
            *(uint4*)&Bs[buf][idx >> 2][(idx & 3) * 8] = rw[slot][i];
        }
    };

    const int NC = DM / 32;
    ldg_chunk(0, 0);
    ldg_chunk(1, 1);
    commit_chunk(0, 0);
    ldg_chunk(2, 0);
    __syncthreads();

    for (int it = 0; it < NC; it++) {
        const int buf = it & 1;
        #pragma unroll
        for (int ks = 0; ks < 2; ks++) {
            const int k0 = ks * 16;
            uint32_t a[2][4];
            #pragma unroll
            for (int mt = 0; mt < 2; mt++) {
                const int r = wm * 32 + mt * 16 + gid;
                a[mt][0] = *(const uint32_t*)&As[buf][r][k0 + 2 * tig];
                a[mt][1] = *(const uint32_t*)&As[buf][r + 8][k0 + 2 * tig];
                a[mt][2] = *(const uint32_t*)&As[buf][r][k0 + 2 * tig + 8];
                a[mt][3] = *(const uint32_t*)&As[buf][r + 8][k0 + 2 * tig + 8];
            }
            #pragma unroll
            for (int nt = 0; nt < 6; nt++) {
                const int n = wn * 48 + nt * 8 + gid;
                const uint32_t b0 = *(const uint32_t*)&Bs[buf][n][k0 + 2 * tig];
                const uint32_t b1 = *(const uint32_t*)&Bs[buf][n][k0 + 2 * tig + 8];
                mma_f16(d[0][nt], a[0], b0, b1);
                mma_f16(d[1][nt], a[1], b0, b1);
            }
        }
        if (it + 1 < NC) commit_chunk((it + 1) & 1, (it + 1) & 1);
        if (it + 3 < NC) ldg_chunk(it + 3, (it + 1) & 1);
        __syncthreads();
    }

    #pragma unroll
    for (int mt = 0; mt < 2; mt++) {
        const int row = m0 + wm * 32 + mt * 16 + gid;
        #pragma unroll
        for (int nt = 0; nt < 6; nt++) {
            const int col0 = wn * 48 + nt * 8;
            __half* dst = (col0 < 64) ? g_q : (col0 < 128) ? g_k : g_v;
            const float scale = (col0 < 64) ? 0.125f : 1.0f;
            const int h0 = (col0 & 63) + 2 * tig;
            const float b0 = bias_sm[col0 + 2 * tig];
            const float b1 = bias_sm[col0 + 2 * tig + 1];
            __half2 w0 = __floats2half2_rn((d[mt][nt][0] + b0) * scale,
                                           (d[mt][nt][1] + b1) * scale);
            __half2 w1 = __floats2half2_rn((d[mt][nt][2] + b0) * scale,
                                           (d[mt][nt][3] + b1) * scale);
            *(uint32_t*)&dst[(size_t)row * NH + h0]       = *(uint32_t*)&w0;
            *(uint32_t*)&dst[(size_t)(row + 8) * NH + h0] = *(uint32_t*)&w1;
        }
    }
}

// =================================================================
// Kernel 1b: transpose V -> g_vt [b][h][s] fp16 (unchanged).
// =================================================================
__global__ __launch_bounds__(256) void vt_kernel()
{
    __shared__ __half t[64][72];
    const int tid = threadIdx.x;
    const int s0  = blockIdx.x * 64;
    const int b   = blockIdx.y;
    const __half* src = g_v + (size_t)b * SEQ * NH;
    __half* dst = g_vt + (size_t)b * NH * SEQ;

    #pragma unroll
    for (int i = 0; i < 2; i++) {
        const int idx = tid + 256 * i;
        const int row = idx >> 3, seg = (idx & 7) * 8;
        *(uint4*)&t[row][seg] = *(const uint4*)&src[(size_t)(s0 + row) * NH + seg];
    }
    __syncthreads();
    #pragma unroll
    for (int i = 0; i < 2; i++) {
        const int idx = tid + 256 * i;
        const int h = idx >> 3, seg = (idx & 7) * 8;
        uint32_t w[4];
        #pragma unroll
        for (int j = 0; j < 4; j++) {
            __half2 hh = __halves2half2(t[seg + 2 * j][h], t[seg + 2 * j + 1][h]);
            w[j] = *(uint32_t*)&hh;
        }
        uint4 o = make_uint4(w[0], w[1], w[2], w[3]);
        *(uint4*)&dst[(size_t)h * SEQ + s0 + seg] = o;
    }
}

// =================================================================
// Kernel 2: split-K causal flash attention (fp16 m16n8k16).
// Grid (64 qtiles, NSP splits, BATCH). 64 threads (2 warps), BQ=32.
// Each split covers ceil(nk/NSP) key tiles; writes partial
// (m, l, unnormalized O) to scratch. Warp-local softmax as R9.
// =================================================================
#define AST 72

__global__ __launch_bounds__(64) void attn_split_kernel()
{
    __shared__ __half ks[2][64][AST];
    __shared__ __half vs[2][64][AST];

    const int tid = threadIdx.x;
    const int qt  = 63 - blockIdx.x;      // heavy blocks first
    const int sp  = blockIdx.y;
    const int b   = blockIdx.z;
    const int q0  = qt * 32;
    const int nk  = (qt >> 1) + 1;
    const int ts  = (nk + NSP - 1) / NSP;
    const int tb  = sp * ts;
    const int te  = (tb + ts < nk) ? (tb + ts) : nk;

    float* PO = g_po + ((size_t)(b * NSP + sp) * SEQ + q0) * NH;
    float* PM = g_pm + (size_t)(b * NSP + sp) * SEQ + q0;
    float* PL = g_pl + (size_t)(b * NSP + sp) * SEQ + q0;

    if (tb >= nk) {
        // empty split: zero weight in combine
        #pragma unroll
        for (int i = 0; i < 4; i++) {
            const int idx = tid + 64 * i;
            const int row = idx >> 3, cg = (idx & 7) * 8;
            float4 z = make_float4(0.f, 0.f, 0.f, 0.f);
            *(float4*)&PO[(size_t)row * NH + cg]     = z;
            *(float4*)&PO[(size_t)row * NH + cg + 4] = z;
        }
        if (tid < 32) { PM[tid] = -1e30f; PL[tid] = 0.f; }
        return;
    }

    const __half* Q  = g_q  + (size_t)b * SEQ * NH;
    const __half* K  = g_k  + (size_t)b * SEQ * NH;
    const __half* VT = g_vt + (size_t)b * NH * SEQ;

    const int wid  = tid >> 5;
    const int lane = tid & 31;
    const int gid  = lane >> 2;
    const int tig  = lane & 3;
    const int r0   = wid * 16 + gid;
    const int r1   = r0 + 8;

    // Q A-fragments straight from global
    uint32_t qa[4][4];
    #pragma unroll
    for (int kc = 0; kc < 4; kc++) {
        const __half* p0 = &Q[(size_t)(q0 + r0) * NH + kc * 16 + 2 * tig];
        const __half* p1 = &Q[(size_t)(q0 + r1) * NH + kc * 16 + 2 * tig];
        qa[kc][0] = *(const uint32_t*)p0;
        qa[kc][1] = *(const uint32_t*)p1;
        qa[kc][2] = *(const uint32_t*)(p0 + 8);
        qa[kc][3] = *(const uint32_t*)(p1 + 8);
    }

    // copy first tile of this split
    {
        const int kb = tb * 64;
        #pragma unroll
        for (int i = 0; i < 8; i++) {
            const int idx = tid + 64 * i;
            const int row = idx >> 3, seg = (idx & 7) * 8;
            *(uint4*)&ks[tb & 1][row][seg] =
                *(const uint4*)&K[(size_t)(kb + row) * NH + seg];
            *(uint4*)&vs[tb & 1][row][seg] =
                *(const uint4*)&VT[(size_t)row * SEQ + kb + seg];
        }
    }
    __syncthreads();

    float m0 = -1e30f, m1 = -1e30f, l0 = 0.f, l1 = 0.f;
    float d_o[8][4];
    #pragma unroll
    for (int nt = 0; nt < 8; nt++)
        #pragma unroll
        for (int c = 0; c < 4; c++) d_o[nt][c] = 0.f;

    for (int t = tb; t < te; t++) {
        if (t + 1 < te) {
            const int kb = (t + 1) * 64;
            const int bn = (t + 1) & 1;
            #pragma unroll
            for (int i = 0; i < 8; i++) {
                const int idx = tid + 64 * i;
                const int row = idx >> 3, seg = (idx & 7) * 8;
                *(uint4*)&ks[bn][row][seg] =
                    *(const uint4*)&K[(size_t)(kb + row) * NH + seg];
                *(uint4*)&vs[bn][row][seg] =
                    *(const uint4*)&VT[(size_t)row * SEQ + kb + seg];
            }
        }

        // ---- S = Q K^T ----
        float sd[8][4];
        #pragma unroll
        for (int nt = 0; nt < 8; nt++)
            #pragma unroll
            for (int c = 0; c < 4; c++) sd[nt][c] = 0.f;
        {
            const __half (*kt)[AST] = ks[t & 1];
            #pragma unroll
            for (int kc = 0; kc < 4; kc++) {
                #pragma unroll
                for (int nt = 0; nt < 8; nt++) {
                    const __half* kp = &kt[8 * nt + gid][kc * 16 + 2 * tig];
                    mma_f16(sd[nt], qa[kc],
                            *(const uint32_t*)kp, *(const uint32_t*)(kp + 8));
                }
            }
        }

        // ---- causal mask (global diagonal tile only) ----
        if (t == nk - 1) {
            #pragma unroll
            for (int nt = 0; nt < 8; nt++) {
                const int kg = t * 64 + 8 * nt + 2 * tig;
                if (kg     > q0 + r0) sd[nt][0] = -1e30f;
                if (kg + 1 > q0 + r0) sd[nt][1] = -1e30f;
                if (kg     > q0 + r1) sd[nt][2] = -1e30f;
                if (kg + 1 > q0 + r1) sd[nt][3] = -1e30f;
            }
        }

        // ---- warp-local online softmax ----
        float t0 = -1e30f, t1 = -1e30f;
        #pragma unroll
        for (int nt = 0; nt < 8; nt++) {
            t0 = fmaxf(t0, fmaxf(sd[nt][0], sd[nt][1]));
            t1 = fmaxf(t1, fmaxf(sd[nt][2], sd[nt][3]));
        }
        t0 = fmaxf(t0, __shfl_xor_sync(0xffffffffu, t0, 1));
        t0 = fmaxf(t0, __shfl_xor_sync(0xffffffffu, t0, 2));
        t1 = fmaxf(t1, __shfl_xor_sync(0xffffffffu, t1, 1));
        t1 = fmaxf(t1, __shfl_xor_sync(0xffffffffu, t1, 2));
        const float mn0 = fmaxf(m0, t0);
        const float mn1 = fmaxf(m1, t1);
        const float f0 = __expf(m0 - mn0);
        const float f1 = __expf(m1 - mn1);
        m0 = mn0; m1 = mn1;
        #pragma unroll
        for (int nt = 0; nt < 8; nt++) {
            d_o[nt][0] *= f0; d_o[nt][1] *= f0;
            d_o[nt][2] *= f1; d_o[nt][3] *= f1;
        }

        uint32_t pa[4][4];
        float s0 = 0.f, s1 = 0.f;
        #pragma unroll
        for (int nt = 0; nt < 8; nt++) {
            __half2 h0 = __floats2half2_rn(__expf(sd[nt][0] - mn0),
                                           __expf(sd[nt][1] - mn0));
            __half2 h1 = __floats2half2_rn(__expf(sd[nt][2] - mn1),
                                           __expf(sd[nt][3] - mn1));
            float2 g0 = __half22float2(h0);
            float2 g1 = __half22float2(h1);
            s0 += g0.x + g0.y;
            s1 += g1.x + g1.y;
            const int kc = nt >> 1;
            if ((nt & 1) == 0) {
                pa[kc][0] = *(uint32_t*)&h0;
                pa[kc][1] = *(uint32_t*)&h1;
            } else {
                pa[kc][2] = *(uint32_t*)&h0;
                pa[kc][3] = *(uint32_t*)&h1;
            }
        }
        s0 += __shfl_xor_sync(0xffffffffu, s0, 1);
        s0 += __shfl_xor_sync(0xffffffffu, s0, 2);
        s1 += __shfl_xor_sync(0xffffffffu, s1, 1);
        s1 += __shfl_xor_sync(0xffffffffu, s1, 2);
        l0 = l0 * f0 + s0;
        l1 = l1 * f1 + s1;

        // ---- O += P V ----
        {
            const __half (*vt)[AST] = vs[t & 1];
            #pragma unroll
            for (int kc = 0; kc < 4; kc++) {
                #pragma unroll
                for (int nt = 0; nt < 8; nt++) {
                    const __half* vp = &vt[8 * nt + gid][kc * 16 + 2 * tig];
                    mma_f16(d_o[nt], pa[kc],
                            *(const uint32_t*)vp, *(const uint32_t*)(vp + 8));
                }
            }
        }
        __syncthreads();
    }

    // ---- write partial (m, l, unnormalized O) ----
    if (tig == 0) {
        PM[r0] = m0; PL[r0] = l0;
        PM[r1] = m1; PL[r1] = l1;
    }
    #pragma unroll
    for (int nt = 0; nt < 8; nt++) {
        const int cc = 8 * nt + 2 * tig;
        *(float2*)&PO[(size_t)r0 * NH + cc] = make_float2(d_o[nt][0], d_o[nt][1]);
        *(float2*)&PO[(size_t)r1 * NH + cc] = make_float2(d_o[nt][2], d_o[nt][3]);
    }
}

// =================================================================
// Kernel 3: combine partials -> out.
// Grid (SEQ/32, BATCH), 256 threads: row = tid>>3, 8 cols per thread.
// =================================================================
__global__ __launch_bounds__(256) void comb_kernel(float* __restrict__ out)
{
    const int tid = threadIdx.x;
    const int s   = blockIdx.x * 32 + (tid >> 3);
    const int b   = blockIdx.y;
    const int cg  = (tid & 7) * 8;

    float m[NSP], l[NSP];
    #pragma unroll
    for (int i = 0; i < NSP; i++) {
        m[i] = g_pm[(size_t)(b * NSP + i) * SEQ + s];
        l[i] = g_pl[(size_t)(b * NSP + i) * SEQ + s];
    }
    float M = m[0];
    #pragma unroll
    for (int i = 1; i < NSP; i++) M = fmaxf(M, m[i]);
    float w[NSP], L = 0.f;
    #pragma unroll
    for (int i = 0; i < NSP; i++) {
        w[i] = __expf(m[i] - M);
        L += w[i] * l[i];
    }
    const float inv = 1.f / L;

    float acc[8] = {0.f, 0.f, 0.f, 0.f, 0.f, 0.f, 0.f, 0.f};
    #pragma unroll
    for (int i = 0; i < NSP; i++) {
        const float* p = &g_po[((size_t)(b * NSP + i) * SEQ + s) * NH + cg];
        float4 o0 = *(const float4*)p;
        float4 o1 = *(const float4*)(p + 4);
        acc[0] += w[i] * o0.x; acc[1] += w[i] * o0.y;
        acc[2] += w[i] * o0.z; acc[3] += w[i] * o0.w;
        acc[4] += w[i] * o1.x; acc[5] += w[i] * o1.y;
        acc[6] += w[i] * o1.z; acc[7] += w[i] * o1.w;
    }
    float* dst = &out[(size_t)(b * SEQ + s) * NH + cg];
    *(float4*)dst       = make_float4(acc[0] * inv, acc[1] * inv,
                                      acc[2] * inv, acc[3] * inv);
    *(float4*)(dst + 4) = make_float4(acc[4] * inv, acc[5] * inv,
                                      acc[6] * inv, acc[7] * inv);
}

// =================================================================
// launch
// =================================================================
extern "C" void kernel_launch(void* const* d_in, const int* in_sizes, int n_in,
                              void* d_out, int out_size)
{
    (void)in_sizes; (void)n_in; (void)out_size;
    const float* x  = (const float*)d_in[0];
    const float* Wq = (const float*)d_in[1];
    const float* bq = (const float*)d_in[2];
    const float* Wk = (const float*)d_in[3];
    const float* bk = (const float*)d_in[4];
    const float* Wv = (const float*)d_in[5];
    const float* bv = (const float*)d_in[6];
    float* out = (float*)d_out;

    wt_kernel<<<dim3(16, 3), 256>>>(Wq, Wk, Wv);
    qkv_mma_kernel<<<(BATCH * SEQ) / 64, 256>>>(x, bq, bk, bv);
    vt_kernel<<<dim3(SEQ / 64, BATCH), 256>>>();
    attn_split_kernel<<<dim3(64, NSP, BATCH), 64>>>();
    comb_kernel<<<dim3(SEQ / 32, BATCH), 256>>>(out);
}